// round 13
// baseline (speedup 1.0000x reference)
#include <cuda_runtime.h>
#include <cuda_bf16.h>
#include <cstdint>

#define HIDDEN      512
#define NUM_LAYERS  8
#define BATCH       16384
#define NUM_OUTPUTS 16

// ---------------- device scratch (allocation-free rule) ----------------
__device__ int8_t g_wq[NUM_LAYERS * HIDDEN * HIDDEN];  // 2 MB int8 weights
__device__ float  g_sw[NUM_LAYERS * HIDDEN];           // per-out-row W scales
__device__ int8_t g_xq[BATCH * HIDDEN];                // 8 MB int8 activations
__device__ float  g_sx[BATCH];                         // per-row act scales

// ---------------- helpers ----------------
__device__ __forceinline__ uint32_t smem_u32(const void* p) {
    return (uint32_t)__cvta_generic_to_shared(p);
}

#define CP_ASYNC16(dst, src) \
    asm volatile("cp.async.cg.shared.global [%0], [%1], 16;" :: "r"(dst), "l"(src))
#define CP_COMMIT() asm volatile("cp.async.commit_group;" ::: "memory")

#define LDSM_X4(r, addr)                                                        \
    asm volatile("ldmatrix.sync.aligned.m8n8.x4.shared.b16 {%0,%1,%2,%3}, [%4];"\
        : "=r"((r)[0]), "=r"((r)[1]), "=r"((r)[2]), "=r"((r)[3]) : "r"(addr))

#define MMAS8(d, a, b0, b1)                                                     \
    asm volatile("mma.sync.aligned.m16n8k32.row.col.s32.s8.s8.s32 "             \
        "{%0,%1,%2,%3},{%4,%5,%6,%7},{%8,%9},{%0,%1,%2,%3};"                    \
        : "+r"((d)[0]), "+r"((d)[1]), "+r"((d)[2]), "+r"((d)[3])                \
        : "r"((a)[0]), "r"((a)[1]), "r"((a)[2]), "r"((a)[3]),                   \
          "r"((b0)), "r"((b1)))

__device__ __forceinline__ float act_lrelu(float x) {
    return (x > 0.f ? x : 0.2f * x) * 1.41421356237309515f;
}
__device__ __forceinline__ uint32_t quant4(const float* v, float r) {
    int a = __float2int_rn(v[0] * r) & 0xFF;
    int b = __float2int_rn(v[1] * r) & 0xFF;
    int c = __float2int_rn(v[2] * r) & 0xFF;
    int d = __float2int_rn(v[3] * r) & 0xFF;
    return (uint32_t)(a | (b << 8) | (c << 16) | (d << 24));
}

// X smem: 512B rows of int8; swizzle 16B quads within each 128B block
__device__ __forceinline__ uint32_t xaddr8(int r, int cb) {
    int q = (cb >> 4) & 7;
    return (uint32_t)(r * 512 + (cb & 384) + ((q ^ (r & 7)) << 4) + (cb & 15));
}
// W stage: 64B rows (k64 int8); q ^= (r>>1)&3
__device__ __forceinline__ uint32_t swzW(int r, int q) {
    return (uint32_t)(r * 64 + ((q ^ ((r >> 1) & 3)) << 4));
}

// ---------------- weight prep: quantize W*wscale to int8 per out-row -------
__global__ void wprep_kernel(const float* __restrict__ w,
                             int8_t* __restrict__ wq, float* __restrict__ sw) {
    int row  = blockIdx.x * 8 + (threadIdx.x >> 5);   // 0..4095
    int lane = threadIdx.x & 31;
    const float ws = 4.4194173824159216e-4f;  // 0.01 / sqrt(512)
    const float* src = w + (size_t)row * HIDDEN + lane * 16;
    float v[16];
    float mx = 0.f;
#pragma unroll
    for (int i = 0; i < 4; i++) {
        float4 f = *(const float4*)(src + i * 4);
        v[i*4+0] = f.x * ws; v[i*4+1] = f.y * ws;
        v[i*4+2] = f.z * ws; v[i*4+3] = f.w * ws;
#pragma unroll
        for (int j = 0; j < 4; j++) mx = fmaxf(mx, fabsf(v[i*4+j]));
    }
#pragma unroll
    for (int o = 16; o > 0; o >>= 1) mx = fmaxf(mx, __shfl_xor_sync(0xffffffff, mx, o));
    float r = (mx > 0.f) ? 127.0f / mx : 0.f;
    uint4 P;
    P.x = quant4(v + 0,  r); P.y = quant4(v + 4,  r);
    P.z = quant4(v + 8,  r); P.w = quant4(v + 12, r);
    *(uint4*)(wq + (size_t)row * HIDDEN + lane * 16) = P;
    if (lane == 0) sw[row] = mx * (1.0f / 127.0f);
}

// ---------------- pixel norm -> int8 + per-row scale ----------------
__global__ void pixnorm_kernel(const float* __restrict__ z,
                               int8_t* __restrict__ xq, float* __restrict__ sx) {
    int row  = blockIdx.x * 8 + threadIdx.y;
    int lane = threadIdx.x;
    const float* zr = z + (size_t)row * HIDDEN + lane * 16;
    float v[16];
    float ss = 0.f;
#pragma unroll
    for (int i = 0; i < 4; i++) {
        float4 f = *(const float4*)(zr + i * 4);
        v[i*4+0] = f.x; v[i*4+1] = f.y; v[i*4+2] = f.z; v[i*4+3] = f.w;
        ss += f.x*f.x + f.y*f.y + f.z*f.z + f.w*f.w;
    }
#pragma unroll
    for (int o = 16; o > 0; o >>= 1) ss += __shfl_xor_sync(0xffffffff, ss, o);
    float s = rsqrtf(ss * (1.0f / 512.0f) + 1e-8f);
    float mx = 0.f;
#pragma unroll
    for (int i = 0; i < 16; i++) { v[i] *= s; mx = fmaxf(mx, fabsf(v[i])); }
#pragma unroll
    for (int o = 16; o > 0; o >>= 1) mx = fmaxf(mx, __shfl_xor_sync(0xffffffff, mx, o));
    float r = (mx > 0.f) ? 127.0f / mx : 0.f;
    uint4 P;
    P.x = quant4(v + 0,  r); P.y = quant4(v + 4,  r);
    P.z = quant4(v + 8,  r); P.w = quant4(v + 12, r);
    *(uint4*)(xq + (size_t)row * HIDDEN + lane * 16) = P;
    if (lane == 0) sx[row] = mx * (1.0f / 127.0f);
}

// ---------------- fused int8 8-layer mapping network -----------------------
// CTA = 64 rows through all 8 layers. X int8 in smem (requantized per layer).
// W int8 streams via 4-stage cp.async, k64 chunks (8/layer, 64 total).
// 256 thr = 8 warps; warp owns 64 cols (wn), all warps share the 64 rows.
#define XS_OFF   0          // 32 KB: X int8, 64 x 512B swizzled
#define SX_OFF   32768      // 256 B: row scales
#define SMX_OFF  33024      // 512 B: 2 x 64 rowmax (uint bits)
#define SW_OFF   33536      // 16 KB: all W scales
#define BI_OFF   49920      // 16 KB: all biases
#define WST_OFF  66304      // 4 x 32 KB W stages
#define SMEM_BYTES (WST_OFF + 4 * 32768)   // 197376

__global__ __launch_bounds__(256, 1) void fused_mlp_kernel(
    const int8_t* __restrict__ Xq, const float* __restrict__ Sx,
    const int8_t* __restrict__ Wq, const float* __restrict__ Sw,
    const float* __restrict__ bias, float* __restrict__ outF)
{
    extern __shared__ char smem[];
    const uint32_t sb = smem_u32(smem);
    const int tid  = threadIdx.x;
    const int lane = tid & 31;
    const int wn   = tid >> 5;            // 0..7 : 64-col slice
    const int m0   = blockIdx.x * 64;

    // ---- prologue loads (group "pre") ----
#pragma unroll
    for (int it = 0; it < 8; it++) {      // X: 2048 quads
        int o = it * 256 + tid;
        int r = o >> 5, qi = o & 31;
        CP_ASYNC16(sb + XS_OFF + xaddr8(r, qi * 16),
                   Xq + (size_t)(m0 + r) * 512 + qi * 16);
    }
    if (tid < 16) CP_ASYNC16(sb + SX_OFF + tid * 16, Sx + m0 + tid * 4);
#pragma unroll
    for (int it = 0; it < 4; it++) {      // SW + BI: 1024 quads each
        int o = it * 256 + tid;
        CP_ASYNC16(sb + SW_OFF + o * 16, Sw + o * 4);
        CP_ASYNC16(sb + BI_OFF + o * 16, bias + o * 4);
    }
    CP_COMMIT();

    auto load_chunk = [&](int g, int s) {
        const int8_t* src = Wq + (size_t)(g >> 3) * HIDDEN * HIDDEN + (g & 7) * 64;
        const uint32_t stb = sb + WST_OFF + s * 32768;
#pragma unroll
        for (int it = 0; it < 8; it++) {  // 2048 quads = 32KB
            int o = it * 256 + tid;
            int n = o >> 2, q = o & 3;
            CP_ASYNC16(stb + swzW(n, q), src + (size_t)n * 512 + q * 16);
        }
        CP_COMMIT();
    };
    load_chunk(0, 0);
    load_chunk(1, 1);
    load_chunk(2, 2);

    if (tid < 128) ((uint32_t*)(smem + SMX_OFF))[tid] = 0;

    int acc[4][8][4];
#pragma unroll
    for (int i = 0; i < 4; i++)
#pragma unroll
        for (int j = 0; j < 8; j++)
#pragma unroll
            for (int k = 0; k < 4; k++) acc[i][j][k] = 0;

    const int t4r = lane >> 2;
    const int t2c = (lane & 3) * 2;
    // ldmatrix addressing
    const int aRowL = lane & 15;          // A: lanes 0-15 rows, 16-31 k+16
    const int aKq   = (lane >> 4) << 4;
    const int bRowL = (lane & 7) + ((lane >> 4) << 3);  // B: n-row
    const int bKq   = (lane >> 3) & 1;                  // B: k-quad half

    float* SXf = (float*)(smem + SX_OFF);

    for (int g = 0; g < 64; g++) {
        int rem = 63 - g;
        if (rem >= 2)      asm volatile("cp.async.wait_group 2;" ::: "memory");
        else if (rem == 1) asm volatile("cp.async.wait_group 1;" ::: "memory");
        else               asm volatile("cp.async.wait_group 0;" ::: "memory");
        __syncthreads();
        if (g + 3 < 64) load_chunk(g + 3, (g + 3) & 3);

        const uint32_t st = sb + WST_OFF + (g & 3) * 32768;
        const int kb0 = (g & 7) * 64;
#pragma unroll
        for (int ks = 0; ks < 2; ks++) {
            uint32_t bf[4][4];
#pragma unroll
            for (int nj = 0; nj < 4; nj++) {
                int rB = wn * 64 + nj * 16 + bRowL;
                LDSM_X4(bf[nj], st + swzW(rB, ks * 2 + bKq));
            }
#pragma unroll
            for (int mi = 0; mi < 4; mi++) {
                int rA = mi * 16 + aRowL;
                uint32_t af[4];
                LDSM_X4(af, sb + XS_OFF + xaddr8(rA, kb0 + ks * 32 + aKq));
#pragma unroll
                for (int nj = 0; nj < 4; nj++) {
                    MMAS8(acc[mi][nj * 2 + 0], af, bf[nj][0], bf[nj][1]);
                    MMAS8(acc[mi][nj * 2 + 1], af, bf[nj][2], bf[nj][3]);
                }
            }
        }

        if ((g & 7) == 7) {
            const int l = g >> 3;
            // per-thread constants (read BEFORE any overwrite)
            float swv[8][2], biv[8][2], sxr[4][2];
#pragma unroll
            for (int ni = 0; ni < 8; ni++) {
                int c0 = wn * 64 + ni * 8 + t2c;
                float2 s2 = *(const float2*)(smem + SW_OFF + (l * 512 + c0) * 4);
                float2 b2 = *(const float2*)(smem + BI_OFF + (l * 512 + c0) * 4);
                swv[ni][0] = s2.x; swv[ni][1] = s2.y;
                biv[ni][0] = b2.x * 0.01f; biv[ni][1] = b2.y * 0.01f;
            }
#pragma unroll
            for (int mi = 0; mi < 4; mi++) {
                sxr[mi][0] = SXf[mi * 16 + t4r];
                sxr[mi][1] = SXf[mi * 16 + t4r + 8];
            }
            __syncthreads();   // all LDSM-from-X done; SMAX buffer ready

            uint32_t* SMX = (uint32_t*)(smem + SMX_OFF) + (l & 1) * 64;
            uint32_t* SMXo = (uint32_t*)(smem + SMX_OFF) + ((l & 1) ^ 1) * 64;

            if (l < NUM_LAYERS - 1) {
                // pass1: row maxima of activated outputs
                float mr[4][2];
#pragma unroll
                for (int mi = 0; mi < 4; mi++) { mr[mi][0] = 0.f; mr[mi][1] = 0.f; }
#pragma unroll
                for (int mi = 0; mi < 4; mi++)
#pragma unroll
                    for (int ni = 0; ni < 8; ni++) {
                        float a0 = act_lrelu((float)acc[mi][ni][0] * sxr[mi][0] * swv[ni][0] + biv[ni][0]);
                        float a1 = act_lrelu((float)acc[mi][ni][1] * sxr[mi][0] * swv[ni][1] + biv[ni][1]);
                        float a2 = act_lrelu((float)acc[mi][ni][2] * sxr[mi][1] * swv[ni][0] + biv[ni][0]);
                        float a3 = act_lrelu((float)acc[mi][ni][3] * sxr[mi][1] * swv[ni][1] + biv[ni][1]);
                        mr[mi][0] = fmaxf(mr[mi][0], fmaxf(fabsf(a0), fabsf(a1)));
                        mr[mi][1] = fmaxf(mr[mi][1], fmaxf(fabsf(a2), fabsf(a3)));
                    }
#pragma unroll
                for (int mi = 0; mi < 4; mi++) {
#pragma unroll
                    for (int h = 0; h < 2; h++) {
                        float m = mr[mi][h];
                        m = fmaxf(m, __shfl_xor_sync(0xffffffff, m, 1));
                        m = fmaxf(m, __shfl_xor_sync(0xffffffff, m, 2));
                        if ((lane & 3) == 0)
                            atomicMax(&SMX[mi * 16 + t4r + h * 8], __float_as_uint(m));
                    }
                }
                __syncthreads();
                // new scales; zero other buffer for next layer
                float r127[4][2];
#pragma unroll
                for (int mi = 0; mi < 4; mi++)
#pragma unroll
                    for (int h = 0; h < 2; h++) {
                        int r = mi * 16 + t4r + h * 8;
                        float mx = __uint_as_float(SMX[r]);
                        r127[mi][h] = (mx > 0.f) ? 127.0f / mx : 0.f;
                        if (wn == 0 && (lane & 3) == 0) SXf[r] = mx * (1.0f / 127.0f);
                    }
                if (tid < 64) SMXo[tid] = 0;
                // pass2: quantize + store int8 X, reset acc
#pragma unroll
                for (int mi = 0; mi < 4; mi++)
#pragma unroll
                    for (int ni = 0; ni < 8; ni++) {
                        int c0 = wn * 64 + ni * 8 + t2c;
                        float a0 = act_lrelu((float)acc[mi][ni][0] * sxr[mi][0] * swv[ni][0] + biv[ni][0]);
                        float a1 = act_lrelu((float)acc[mi][ni][1] * sxr[mi][0] * swv[ni][1] + biv[ni][1]);
                        float a2 = act_lrelu((float)acc[mi][ni][2] * sxr[mi][1] * swv[ni][0] + biv[ni][0]);
                        float a3 = act_lrelu((float)acc[mi][ni][3] * sxr[mi][1] * swv[ni][1] + biv[ni][1]);
                        int r = mi * 16 + t4r;
                        int q0 = __float2int_rn(a0 * r127[mi][0]) & 0xFF;
                        int q1 = __float2int_rn(a1 * r127[mi][0]) & 0xFF;
                        int q2 = __float2int_rn(a2 * r127[mi][1]) & 0xFF;
                        int q3 = __float2int_rn(a3 * r127[mi][1]) & 0xFF;
                        *(uint16_t*)(smem + XS_OFF + xaddr8(r,     c0)) = (uint16_t)(q0 | (q1 << 8));
                        *(uint16_t*)(smem + XS_OFF + xaddr8(r + 8, c0)) = (uint16_t)(q2 | (q3 << 8));
#pragma unroll
                        for (int k = 0; k < 4; k++) acc[mi][ni][k] = 0;
                    }
                // loop-top __syncthreads orders X writes before next LDSM
            } else {
                // final: fp32 staging (64 x 2048B @0) + coalesced broadcast
#pragma unroll
                for (int mi = 0; mi < 4; mi++)
#pragma unroll
                    for (int ni = 0; ni < 8; ni++) {
                        int c0 = wn * 64 + ni * 8 + t2c;
                        float a0 = act_lrelu((float)acc[mi][ni][0] * sxr[mi][0] * swv[ni][0] + biv[ni][0]);
                        float a1 = act_lrelu((float)acc[mi][ni][1] * sxr[mi][0] * swv[ni][1] + biv[ni][1]);
                        float a2 = act_lrelu((float)acc[mi][ni][2] * sxr[mi][1] * swv[ni][0] + biv[ni][0]);
                        float a3 = act_lrelu((float)acc[mi][ni][3] * sxr[mi][1] * swv[ni][1] + biv[ni][1]);
                        int r = mi * 16 + t4r;
                        *(float2*)(smem + (size_t)r * 2048 + c0 * 4)       = make_float2(a0, a1);
                        *(float2*)(smem + (size_t)(r + 8) * 2048 + c0 * 4) = make_float2(a2, a3);
                    }
                __syncthreads();
                for (int it = 0; it < 512; it++) {
                    int idx = it * 256 + tid;
                    int f4  = idx & 127;
                    int j   = (idx >> 7) & 15;
                    int row = idx >> 11;
                    float4 v = *(const float4*)(smem + (size_t)row * 2048 + f4 * 16);
                    *(float4*)(outF + ((size_t)(m0 + row) * NUM_OUTPUTS + j) * HIDDEN
                                    + f4 * 4) = v;
                }
            }
        }
    }
}

// ---------------------------------------------------------------------------
extern "C" void kernel_launch(void* const* d_in, const int* in_sizes, int n_in,
                              void* d_out, int out_size) {
    const float* z    = (const float*)d_in[0];
    const float* w    = (const float*)d_in[1];
    const float* bias = (const float*)d_in[2];
    float* out = (float*)d_out;

    int8_t *wq, *xq;
    float *sw, *sx;
    cudaGetSymbolAddress((void**)&wq, g_wq);
    cudaGetSymbolAddress((void**)&sw, g_sw);
    cudaGetSymbolAddress((void**)&xq, g_xq);
    cudaGetSymbolAddress((void**)&sx, g_sx);

    cudaFuncSetAttribute(fused_mlp_kernel,
                         cudaFuncAttributeMaxDynamicSharedMemorySize, SMEM_BYTES);

    // 1) quantize weights (per out-row absmax)
    wprep_kernel<<<NUM_LAYERS * HIDDEN / 8, 256>>>(w, wq, sw);
    // 2) pixel norm + quantize activations (per row absmax)
    pixnorm_kernel<<<BATCH / 8, dim3(32, 8)>>>(z, xq, sx);
    // 3) fused int8 8-layer network + broadcast
    fused_mlp_kernel<<<BATCH / 64, 256, SMEM_BYTES>>>(xq, sx, wq, sw, bias, out);
}

// round 14
// speedup vs baseline: 1.3047x; 1.3047x over previous
#include <cuda_runtime.h>
#include <cuda_fp16.h>
#include <cstdint>

#define HIDDEN      512
#define NUM_LAYERS  8
#define BATCH       16384
#define NUM_OUTPUTS 16

// ---------------- device scratch (allocation-free rule) ----------------
__device__ __half g_wh[NUM_LAYERS * HIDDEN * HIDDEN];  // 4 MB fp16 weights
__device__ __half g_xh[BATCH * HIDDEN];                // 16 MB fp16 activations

// ---------------- helpers ----------------
__device__ __forceinline__ uint32_t smem_u32(const void* p) {
    return (uint32_t)__cvta_generic_to_shared(p);
}

#define CP_ASYNC16(dst, src) \
    asm volatile("cp.async.cg.shared.global [%0], [%1], 16;" :: "r"(dst), "l"(src))
#define CP_COMMIT() asm volatile("cp.async.commit_group;" ::: "memory")

#define LDSM_X4(r, addr)                                                        \
    asm volatile("ldmatrix.sync.aligned.m8n8.x4.shared.b16 {%0,%1,%2,%3}, [%4];"\
        : "=r"((r)[0]), "=r"((r)[1]), "=r"((r)[2]), "=r"((r)[3]) : "r"(addr))

// fp16-accumulate HMMA: d = a*b + d, all fp16 (C/D = 2 regs)
#define MMAF16(d, a, b0, b1)                                                    \
    asm volatile("mma.sync.aligned.m16n8k16.row.col.f16.f16.f16.f16 "           \
        "{%0,%1},{%2,%3,%4,%5},{%6,%7},{%0,%1};"                                \
        : "+r"((d)[0]), "+r"((d)[1])                                            \
        : "r"((a)[0]), "r"((a)[1]), "r"((a)[2]), "r"((a)[3]),                   \
          "r"((b0)), "r"((b1)))

__device__ __forceinline__ uint32_t pk2h(float a, float b) {
    __half2 t = __floats2half2_rn(a, b);
    return *reinterpret_cast<uint32_t*>(&t);
}
__device__ __forceinline__ float act_lrelu(float x) {
    return (x > 0.f ? x : 0.2f * x) * 1.41421356237309515f;
}

// X smem: 1024B rows; within each 128B block, 16B quad q ^= (r&7)
__device__ __forceinline__ uint32_t xbyte(int r, int cbyte) {
    int blk = cbyte >> 7;
    int q   = (cbyte >> 4) & 7;
    int o   = cbyte & 15;
    return (uint32_t)(r * 1024 + blk * 128 + ((q ^ (r & 7)) << 4) + o);
}
// W stage: 64B rows (k32 fp16); q ^= (r>>1)&3
__device__ __forceinline__ uint32_t swzB(int r, int q) {
    return (uint32_t)(r * 64 + ((q ^ ((r >> 1) & 3)) << 4));
}

// ---------------- weight prep: W*wscale -> fp16 ----------------
__global__ void wprep_kernel(const float* __restrict__ w, __half* __restrict__ wh) {
    size_t base = ((size_t)blockIdx.x * 256 + threadIdx.x) * 4;
    const float ws = 4.4194173824159216e-4f;  // 0.01 / sqrt(512)
    float4 v = *(const float4*)(w + base);
    uint2 H;
    H.x = pk2h(v.x * ws, v.y * ws);
    H.y = pk2h(v.z * ws, v.w * ws);
    *(uint2*)(wh + base) = H;
}

// ---------------- pixel norm -> fp16 ----------------
__global__ void pixnorm_kernel(const float* __restrict__ z, __half* __restrict__ xh) {
    int row  = blockIdx.x * 8 + threadIdx.y;
    int lane = threadIdx.x;
    const float4* zr = (const float4*)(z + (size_t)row * HIDDEN);
    float4 v[4];
    float ss = 0.f;
#pragma unroll
    for (int i = 0; i < 4; i++) {
        v[i] = zr[lane + 32 * i];
        ss += v[i].x * v[i].x + v[i].y * v[i].y + v[i].z * v[i].z + v[i].w * v[i].w;
    }
#pragma unroll
    for (int o = 16; o > 0; o >>= 1) ss += __shfl_xor_sync(0xffffffff, ss, o);
    float s = rsqrtf(ss * (1.0f / 512.0f) + 1e-8f);
#pragma unroll
    for (int i = 0; i < 4; i++) {
        uint2 H;
        H.x = pk2h(v[i].x * s, v[i].y * s);
        H.y = pk2h(v[i].z * s, v[i].w * s);
        *(uint2*)(xh + (size_t)row * HIDDEN + 4 * (lane + 32 * i)) = H;
    }
}

// ---------------- fused 8-layer mapping network (fp16 acc) -----------------
// One CTA: 128 rows x all 512 cols through all 8 layers. Grid = 128 = 1 wave.
// 512 thr = 16 warps as 2(M) x 8(N); warp tile 64x64; fp16 accumulators.
// X fp16 in smem (128 x 1024B swizzled, rewritten per layer).
// W streams k32 chunks (512 x 64B = 32KB), 3 stages, cp.async depth-2.
#define X_OFF    0                        // 128 KB
#define WST_OFF  131072
#define WSTAGE_B 32768
#define SMEM_BYTES (WST_OFF + 3 * WSTAGE_B)   // 229376
#define NCH      (NUM_LAYERS * 16)            // 128 chunks

__global__ __launch_bounds__(512, 1) void fused_mlp_kernel(
    const __half* __restrict__ Xh, const __half* __restrict__ Wh,
    const float* __restrict__ bias, float* __restrict__ outF)
{
    extern __shared__ char smem[];
    const uint32_t sb = smem_u32(smem);
    const int tid  = threadIdx.x;
    const int lane = tid & 31;
    const int warp = tid >> 5;
    const int wm   = warp >> 3;           // 0..1 : 64-row half
    const int wn   = warp & 7;            // 0..7 : 64-col slice
    const int m0   = blockIdx.x * 128;

    // ---- initial X load: 128 rows x 64 quads = 8192 quads ----
#pragma unroll
    for (int it = 0; it < 16; it++) {
        int o = it * 512 + tid;
        int r = o >> 6, kq = o & 63;
        CP_ASYNC16(sb + X_OFF + xbyte(r, kq * 16),
                   Xh + (size_t)(m0 + r) * HIDDEN + kq * 8);
    }
    CP_COMMIT();

    auto load_chunk = [&](int g, int s) {
        const __half* src = Wh + (size_t)(g >> 4) * HIDDEN * HIDDEN + (g & 15) * 32;
        const uint32_t stb = sb + WST_OFF + s * WSTAGE_B;
#pragma unroll
        for (int it = 0; it < 4; it++) {  // 2048 quads = 32KB
            int o = it * 512 + tid;
            int n = o >> 2, q = o & 3;
            CP_ASYNC16(stb + swzB(n, q), src + (size_t)n * HIDDEN + q * 8);
        }
        CP_COMMIT();
    };
    load_chunk(0, 0);
    load_chunk(1, 1);

    uint32_t acc[4][8][2];
#pragma unroll
    for (int i = 0; i < 4; i++)
#pragma unroll
        for (int j = 0; j < 8; j++) { acc[i][j][0] = 0; acc[i][j][1] = 0; }

    const int aRowL = lane & 15;
    const int aKq   = lane >> 4;
    const int bRowL = (lane & 7) + ((lane >> 4) << 3);
    const int bKq   = (lane >> 3) & 1;
    const int t4r   = lane >> 2;
    const int t2c   = (lane & 3) * 2;

    for (int g = 0; g < NCH; g++) {
        if (g >= NCH - 2) asm volatile("cp.async.wait_group 0;" ::: "memory");
        else              asm volatile("cp.async.wait_group 1;" ::: "memory");
        __syncthreads();
        if (g + 2 < NCH) load_chunk(g + 2, (g + 2) % 3);

        const uint32_t st  = sb + WST_OFF + (g % 3) * WSTAGE_B;
        const int kq0 = (g & 15) * 4;     // first 16B quad of this k32 chunk
#pragma unroll
        for (int kh = 0; kh < 2; kh++) {
            uint32_t bf[4][4];
#pragma unroll
            for (int nj = 0; nj < 4; nj++) {
                int rB = wn * 64 + nj * 16 + bRowL;
                LDSM_X4(bf[nj], st + swzB(rB, kh * 2 + bKq));
            }
#pragma unroll
            for (int mi = 0; mi < 4; mi++) {
                int rA = wm * 64 + mi * 16 + aRowL;
                uint32_t af[4];
                LDSM_X4(af, sb + X_OFF + xbyte(rA, (kq0 + kh * 2 + aKq) * 16));
#pragma unroll
                for (int nj = 0; nj < 4; nj++) {
                    MMAF16(acc[mi][nj * 2 + 0], af, bf[nj][0], bf[nj][1]);
                    MMAF16(acc[mi][nj * 2 + 1], af, bf[nj][2], bf[nj][3]);
                }
            }
        }

        if ((g & 15) == 15) {
            const int l = g >> 4;
            const float* bl = bias + l * HIDDEN;
            __syncthreads();              // all LDSM-from-X of this layer done

            if (l < NUM_LAYERS - 1) {
                // bias + lrelu -> fp16 -> X in place
#pragma unroll
                for (int ni = 0; ni < 8; ni++) {
                    const int c0 = wn * 64 + ni * 8 + t2c;
                    float2 b2 = *(const float2*)(bl + c0);
                    const float bb0 = b2.x * 0.01f, bb1 = b2.y * 0.01f;
#pragma unroll
                    for (int mi = 0; mi < 4; mi++) {
                        const int r = wm * 64 + mi * 16 + t4r;
                        float2 p0 = __half22float2(*(__half2*)&acc[mi][ni][0]);
                        float2 p1 = __half22float2(*(__half2*)&acc[mi][ni][1]);
                        float v0 = act_lrelu(p0.x + bb0);
                        float v1 = act_lrelu(p0.y + bb1);
                        float v2 = act_lrelu(p1.x + bb0);
                        float v3 = act_lrelu(p1.y + bb1);
                        *(uint32_t*)(smem + X_OFF + xbyte(r,     c0 * 2)) = pk2h(v0, v1);
                        *(uint32_t*)(smem + X_OFF + xbyte(r + 8, c0 * 2)) = pk2h(v2, v3);
                        acc[mi][ni][0] = 0; acc[mi][ni][1] = 0;
                    }
                }
                // next loop-top __syncthreads orders X before LDSM
            } else {
                // final: two 64-row halves staged fp32 in smem, coalesced bcast
#pragma unroll
                for (int h = 0; h < 2; h++) {
                    if (wm == h) {
#pragma unroll
                        for (int ni = 0; ni < 8; ni++) {
                            const int c0 = wn * 64 + ni * 8 + t2c;
                            float2 b2 = *(const float2*)(bl + c0);
                            const float bb0 = b2.x * 0.01f, bb1 = b2.y * 0.01f;
#pragma unroll
                            for (int mi = 0; mi < 4; mi++) {
                                const int r = mi * 16 + t4r;  // 0..63 within half
                                float2 p0 = __half22float2(*(__half2*)&acc[mi][ni][0]);
                                float2 p1 = __half22float2(*(__half2*)&acc[mi][ni][1]);
                                *(float2*)(smem + (size_t)r * 2048 + c0 * 4) =
                                    make_float2(act_lrelu(p0.x + bb0), act_lrelu(p0.y + bb1));
                                *(float2*)(smem + (size_t)(r + 8) * 2048 + c0 * 4) =
                                    make_float2(act_lrelu(p1.x + bb0), act_lrelu(p1.y + bb1));
                            }
                        }
                    }
                    __syncthreads();
                    // stream 64 rows x 16 copies x 512 floats, coalesced float4
                    for (int it = 0; it < 256; it++) {
                        int idx = it * 512 + tid;       // 0..131071 float4s
                        int f4  = idx & 127;
                        int j   = (idx >> 7) & 15;
                        int row = idx >> 11;            // 0..63
                        float4 v = *(const float4*)(smem + (size_t)row * 2048 + f4 * 16);
                        *(float4*)(outF + ((size_t)(m0 + h * 64 + row) * NUM_OUTPUTS + j)
                                        * HIDDEN + f4 * 4) = v;
                    }
                    __syncthreads();
                }
            }
        }
    }
}

// ---------------------------------------------------------------------------
extern "C" void kernel_launch(void* const* d_in, const int* in_sizes, int n_in,
                              void* d_out, int out_size) {
    const float* z    = (const float*)d_in[0];
    const float* w    = (const float*)d_in[1];
    const float* bias = (const float*)d_in[2];
    float* out = (float*)d_out;

    __half *wh, *xh;
    cudaGetSymbolAddress((void**)&wh, g_wh);
    cudaGetSymbolAddress((void**)&xh, g_xh);

    cudaFuncSetAttribute(fused_mlp_kernel,
                         cudaFuncAttributeMaxDynamicSharedMemorySize, SMEM_BYTES);

    // 1) weight scale -> fp16
    wprep_kernel<<<2048, 256>>>(w, wh);
    // 2) pixel norm -> fp16
    pixnorm_kernel<<<BATCH / 8, dim3(32, 8)>>>(z, xh);
    // 3) fused 8-layer network + broadcast (128 CTAs = 1 wave)
    fused_mlp_kernel<<<BATCH / 128, 512, SMEM_BYTES>>>(xh, wh, bias, out);
}

// round 15
// speedup vs baseline: 1.9733x; 1.5124x over previous
#include <cuda_runtime.h>
#include <cuda_fp16.h>
#include <cstdint>

#define HIDDEN      512
#define NUM_LAYERS  8
#define BATCH       16384
#define NUM_OUTPUTS 16

// ---------------- device scratch (allocation-free rule) ----------------
__device__ __half g_wh[NUM_LAYERS * HIDDEN * HIDDEN];  // 4 MB fp16 weights
__device__ __half g_xh[BATCH * HIDDEN];                // 16 MB fp16 activations

// ---------------- helpers ----------------
__device__ __forceinline__ uint32_t smem_u32(const void* p) {
    return (uint32_t)__cvta_generic_to_shared(p);
}

#define CP_ASYNC16(dst, src) \
    asm volatile("cp.async.cg.shared.global [%0], [%1], 16;" :: "r"(dst), "l"(src))
#define CP_COMMIT() asm volatile("cp.async.commit_group;" ::: "memory")

#define LDSM_X4(r, addr)                                                        \
    asm volatile("ldmatrix.sync.aligned.m8n8.x4.shared.b16 {%0,%1,%2,%3}, [%4];"\
        : "=r"((r)[0]), "=r"((r)[1]), "=r"((r)[2]), "=r"((r)[3]) : "r"(addr))

// fp16-accumulate HMMA: d = a*b + d, all fp16 (C/D = 2 regs)
#define MMAF16(d, a, b0, b1)                                                    \
    asm volatile("mma.sync.aligned.m16n8k16.row.col.f16.f16.f16.f16 "           \
        "{%0,%1},{%2,%3,%4,%5},{%6,%7},{%0,%1};"                                \
        : "+r"((d)[0]), "+r"((d)[1])                                            \
        : "r"((a)[0]), "r"((a)[1]), "r"((a)[2]), "r"((a)[3]),                   \
          "r"((b0)), "r"((b1)))

__device__ __forceinline__ uint32_t pk2h(float a, float b) {
    __half2 t = __floats2half2_rn(a, b);
    return *reinterpret_cast<uint32_t*>(&t);
}
__device__ __forceinline__ float act_lrelu(float x) {
    return (x > 0.f ? x : 0.2f * x) * 1.41421356237309515f;
}

// W stage: 64B rows of 4x16B quads; q ^= (r>>1)&3
__device__ __forceinline__ uint32_t swzB(int r, int q) {
    return (uint32_t)(r * 64 + ((q ^ ((r >> 1) & 3)) << 4));
}
// X: 1024B rows; within each 128B block, 16B quad q ^= (r&7)
__device__ __forceinline__ uint32_t xbyte(int r, int cbyte) {
    int blk = cbyte >> 7;
    int q   = (cbyte >> 4) & 7;
    int o   = cbyte & 15;
    return (uint32_t)(r * 1024 + blk * 128 + ((q ^ (r & 7)) << 4) + o);
}

// ---------------- weight prep: W*wscale -> fp16 ----------------
__global__ void wprep_kernel(const float* __restrict__ w, __half* __restrict__ wh) {
    size_t base = ((size_t)blockIdx.x * 256 + threadIdx.x) * 4;
    const float ws = 4.4194173824159216e-4f;  // 0.01 / sqrt(512)
    float4 v = *(const float4*)(w + base);
    uint2 H;
    H.x = pk2h(v.x * ws, v.y * ws);
    H.y = pk2h(v.z * ws, v.w * ws);
    *(uint2*)(wh + base) = H;
}

// ---------------- pixel norm -> fp16 ----------------
__global__ void pixnorm_kernel(const float* __restrict__ z, __half* __restrict__ xh) {
    int row  = blockIdx.x * 8 + threadIdx.y;
    int lane = threadIdx.x;
    const float4* zr = (const float4*)(z + (size_t)row * HIDDEN);
    float4 v[4];
    float ss = 0.f;
#pragma unroll
    for (int i = 0; i < 4; i++) {
        v[i] = zr[lane + 32 * i];
        ss += v[i].x * v[i].x + v[i].y * v[i].y + v[i].z * v[i].z + v[i].w * v[i].w;
    }
#pragma unroll
    for (int o = 16; o > 0; o >>= 1) ss += __shfl_xor_sync(0xffffffff, ss, o);
    float s = rsqrtf(ss * (1.0f / 512.0f) + 1e-8f);
#pragma unroll
    for (int i = 0; i < 4; i++) {
        uint2 H;
        H.x = pk2h(v[i].x * s, v[i].y * s);
        H.y = pk2h(v[i].z * s, v[i].w * s);
        *(uint2*)(xh + (size_t)row * HIDDEN + 4 * (lane + 32 * i)) = H;
    }
}

// ---------------- fused 8-layer mapping network (fp16 acc) -----------------
// One CTA owns 64 batch rows through ALL 8 layers (R11 geometry).
// 256 threads = 8 warps; warp = 64-col slice (wn), warp tile 64x64.
// X fp16 in smem (64 x 1024B swizzled, rewritten per layer).
// W streams k32 chunks (512 x 64B = 32KB), 3 stages, cp.async depth-2.
#define X_OFF    0
#define WST_OFF  65536
#define WSTAGE_B 32768
#define SMEM_BYTES (WST_OFF + 3 * WSTAGE_B)   // 163840
#define NCH      (NUM_LAYERS * 16)            // 128 chunks

__global__ __launch_bounds__(256, 1) void fused_mlp_kernel(
    const __half* __restrict__ Xh, const __half* __restrict__ Wh,
    const float* __restrict__ bias, float* __restrict__ outF)
{
    extern __shared__ char smem[];
    const uint32_t sb = smem_u32(smem);
    const int tid  = threadIdx.x;
    const int lane = tid & 31;
    const int wn   = tid >> 5;            // 0..7 : 64-col slice
    const int m0   = blockIdx.x * 64;

    // ---- initial X load: 64 rows x 64 quads = 4096 quads ----
#pragma unroll
    for (int it = 0; it < 16; it++) {
        int o = it * 256 + tid;
        int r = o >> 6, kq = o & 63;
        CP_ASYNC16(sb + X_OFF + xbyte(r, kq * 16),
                   Xh + (size_t)(m0 + r) * HIDDEN + kq * 8);
    }
    CP_COMMIT();

    auto load_chunk = [&](int g, int s) {
        const __half* src = Wh + (size_t)(g >> 4) * HIDDEN * HIDDEN + (g & 15) * 32;
        const uint32_t stb = sb + WST_OFF + s * WSTAGE_B;
#pragma unroll
        for (int it = 0; it < 8; it++) {  // 2048 quads = 32KB
            int o = it * 256 + tid;
            int n = o >> 2, q = o & 3;
            CP_ASYNC16(stb + swzB(n, q), src + (size_t)n * HIDDEN + q * 8);
        }
        CP_COMMIT();
    };
    load_chunk(0, 0);
    load_chunk(1, 1);

    uint32_t acc[4][8][2];
#pragma unroll
    for (int i = 0; i < 4; i++)
#pragma unroll
        for (int j = 0; j < 8; j++) { acc[i][j][0] = 0; acc[i][j][1] = 0; }

    const int aRowL = lane & 15;
    const int aKq   = lane >> 4;
    const int bRowL = (lane & 7) + ((lane >> 4) << 3);
    const int bKq   = (lane >> 3) & 1;
    const int t4r   = lane >> 2;
    const int t2c   = (lane & 3) * 2;

    for (int g = 0; g < NCH; g++) {
        if (g >= NCH - 2) asm volatile("cp.async.wait_group 0;" ::: "memory");
        else              asm volatile("cp.async.wait_group 1;" ::: "memory");
        __syncthreads();
        if (g + 2 < NCH) load_chunk(g + 2, (g + 2) % 3);

        const uint32_t st  = sb + WST_OFF + (g % 3) * WSTAGE_B;
        const int kq0 = (g & 15) * 4;     // first 16B quad of this k32 chunk in X
#pragma unroll
        for (int kh = 0; kh < 2; kh++) {
            uint32_t bf[4][4];
#pragma unroll
            for (int nj = 0; nj < 4; nj++) {
                int rB = wn * 64 + nj * 16 + bRowL;
                LDSM_X4(bf[nj], st + swzB(rB, kh * 2 + bKq));
            }
#pragma unroll
            for (int mi = 0; mi < 4; mi++) {
                int rA = mi * 16 + aRowL;
                uint32_t af[4];
                LDSM_X4(af, sb + X_OFF + xbyte(rA, (kq0 + kh * 2 + aKq) * 16));
#pragma unroll
                for (int nj = 0; nj < 4; nj++) {
                    MMAF16(acc[mi][nj * 2 + 0], af, bf[nj][0], bf[nj][1]);
                    MMAF16(acc[mi][nj * 2 + 1], af, bf[nj][2], bf[nj][3]);
                }
            }
        }

        if ((g & 15) == 15) {
            const int l = g >> 4;
            const float* bl = bias + l * HIDDEN;
            __syncthreads();              // all LDSM-from-X of this layer done

            if (l < NUM_LAYERS - 1) {
                // bias + lrelu -> fp16 -> X in place
#pragma unroll
                for (int ni = 0; ni < 8; ni++) {
                    const int c0 = wn * 64 + ni * 8 + t2c;
                    float2 b2 = *(const float2*)(bl + c0);
                    const float bb0 = b2.x * 0.01f, bb1 = b2.y * 0.01f;
#pragma unroll
                    for (int mi = 0; mi < 4; mi++) {
                        const int r = mi * 16 + t4r;
                        float2 p0 = __half22float2(*(__half2*)&acc[mi][ni][0]);
                        float2 p1 = __half22float2(*(__half2*)&acc[mi][ni][1]);
                        float v0 = act_lrelu(p0.x + bb0);
                        float v1 = act_lrelu(p0.y + bb1);
                        float v2 = act_lrelu(p1.x + bb0);
                        float v3 = act_lrelu(p1.y + bb1);
                        *(uint32_t*)(smem + X_OFF + xbyte(r,     c0 * 2)) = pk2h(v0, v1);
                        *(uint32_t*)(smem + X_OFF + xbyte(r + 8, c0 * 2)) = pk2h(v2, v3);
                        acc[mi][ni][0] = 0; acc[mi][ni][1] = 0;
                    }
                }
                // next loop-top __syncthreads orders X before LDSM
            } else {
                // final: fp32 staging (64 x 2048B @0, 128KB) + coalesced bcast
#pragma unroll
                for (int ni = 0; ni < 8; ni++) {
                    const int c0 = wn * 64 + ni * 8 + t2c;
                    float2 b2 = *(const float2*)(bl + c0);
                    const float bb0 = b2.x * 0.01f, bb1 = b2.y * 0.01f;
#pragma unroll
                    for (int mi = 0; mi < 4; mi++) {
                        const int r = mi * 16 + t4r;
                        float2 p0 = __half22float2(*(__half2*)&acc[mi][ni][0]);
                        float2 p1 = __half22float2(*(__half2*)&acc[mi][ni][1]);
                        *(float2*)(smem + (size_t)r * 2048 + c0 * 4) =
                            make_float2(act_lrelu(p0.x + bb0), act_lrelu(p0.y + bb1));
                        *(float2*)(smem + (size_t)(r + 8) * 2048 + c0 * 4) =
                            make_float2(act_lrelu(p1.x + bb0), act_lrelu(p1.y + bb1));
                    }
                }
                __syncthreads();
                // stream 64 rows x 16 copies, fully coalesced float4
                for (int it = 0; it < 512; it++) {
                    int idx = it * 256 + tid;        // 0..131071 float4s
                    int f4  = idx & 127;
                    int j   = (idx >> 7) & 15;
                    int row = idx >> 11;             // 0..63
                    float4 v = *(const float4*)(smem + (size_t)row * 2048 + f4 * 16);
                    *(float4*)(outF + ((size_t)(m0 + row) * NUM_OUTPUTS + j) * HIDDEN
                                    + f4 * 4) = v;
                }
            }
        }
    }
}

// ---------------------------------------------------------------------------
extern "C" void kernel_launch(void* const* d_in, const int* in_sizes, int n_in,
                              void* d_out, int out_size) {
    const float* z    = (const float*)d_in[0];
    const float* w    = (const float*)d_in[1];
    const float* bias = (const float*)d_in[2];
    float* out = (float*)d_out;

    __half *wh, *xh;
    cudaGetSymbolAddress((void**)&wh, g_wh);
    cudaGetSymbolAddress((void**)&xh, g_xh);

    cudaFuncSetAttribute(fused_mlp_kernel,
                         cudaFuncAttributeMaxDynamicSharedMemorySize, SMEM_BYTES);

    // 1) weight scale -> fp16
    wprep_kernel<<<2048, 256>>>(w, wh);
    // 2) pixel norm -> fp16
    pixnorm_kernel<<<BATCH / 8, dim3(32, 8)>>>(z, xh);
    // 3) fused 8-layer network + broadcast (256 CTAs, 64 rows each)
    fused_mlp_kernel<<<BATCH / 64, 256, SMEM_BYTES>>>(xh, wh, bias, out);
}